// round 17
// baseline (speedup 1.0000x reference)
#include <cuda_runtime.h>
#include <cuda_bf16.h>
#include <cuda_fp16.h>
#include <math.h>
#include <stdint.h>

// ---------------- problem constants ----------------
constexpr int BB   = 32;
constexpr int NSEQ = 256;
constexpr int DIM  = 1024;
constexpr int NH   = 16;
constexpr int HDIM = 64;
constexpr int CDIM = 1024;
constexpr int NE   = 4;
constexpr int DFFC = 4096;
constexpr int RHC  = 2048;
constexpr int TT   = BB * NSEQ;   // 8192 tokens

// ---------------- scratch (device globals; no allocation allowed) ----------------
__device__ float  g_h1[TT * DIM];
__device__ __half g_qkv[(size_t)TT * 3 * DIM];
__device__ float  g_o[TT * DIM];
__device__ float  g_x1[TT * DIM];
__device__ float  g_h2[TT * DIM];
__device__ float  g_condc[BB * RHC];
__device__ float  g_gh[(size_t)TT * RHC];
__device__ __half g_hid[(size_t)NE * TT * DFFC];
__device__ __half g_eout[(size_t)NE * TT * DIM];
__device__ int    g_cnt[NE];
__device__ int    g_idx[NE * TT];
__device__ int2   g_te[TT];
__device__ float2 g_tw[TT];

// pre-split K-major weights: [N][K] fp16; lo only where needed (fc1)
__device__ __half g_wqkv_h[(size_t)3 * DIM * DIM];
__device__ __half g_wproj_h[(size_t)DIM * DIM];
__device__ __half g_wfc1_h[(size_t)RHC * DIM];
__device__ __half g_wfc1_l[(size_t)RHC * DIM];
__device__ __half g_we1_h[(size_t)NE * DFFC * DIM];
__device__ __half g_we2_h[(size_t)NE * DIM * DFFC];

// ---------------- helpers ----------------
__device__ __forceinline__ float warpsum(float v) {
    #pragma unroll
    for (int o = 16; o; o >>= 1) v += __shfl_xor_sync(0xFFFFFFFFu, v, o);
    return v;
}
__device__ __forceinline__ float warpmax(float v) {
    #pragma unroll
    for (int o = 16; o; o >>= 1) v = fmaxf(v, __shfl_xor_sync(0xFFFFFFFFu, v, o));
    return v;
}
__device__ __forceinline__ float gelu_f(float x) {
    return 0.5f * x * (1.0f + erff(x * 0.70710678118654752f));
}
__device__ __forceinline__ void hsplit2(float x0, float x1, uint32_t& hi, uint32_t& lo) {
    __half2 h = __floats2half2_rn(x0, x1);
    float r0 = x0 - __half2float(__low2half(h));
    float r1 = x1 - __half2float(__high2half(h));
    __half2 l = __floats2half2_rn(r0, r1);
    hi = *reinterpret_cast<uint32_t*>(&h);
    lo = *reinterpret_cast<uint32_t*>(&l);
}
__device__ __forceinline__ uint32_t hpack2(float x0, float x1) {
    __half2 h = __floats2half2_rn(x0, x1);
    return *reinterpret_cast<uint32_t*>(&h);
}
__device__ __forceinline__ void bfsplit2(float x0, float x1, uint32_t& hi, uint32_t& lo) {
    __nv_bfloat162 h = __floats2bfloat162_rn(x0, x1);
    float r0 = x0 - __bfloat162float(h.x);
    float r1 = x1 - __bfloat162float(h.y);
    __nv_bfloat162 l = __floats2bfloat162_rn(r0, r1);
    hi = *reinterpret_cast<uint32_t*>(&h);
    lo = *reinterpret_cast<uint32_t*>(&l);
}
__device__ __forceinline__ void mma16bf(float* c, const uint32_t* a, const uint32_t* b) {
    asm("mma.sync.aligned.m16n8k16.row.col.f32.bf16.bf16.f32 "
        "{%0,%1,%2,%3}, {%4,%5,%6,%7}, {%8,%9}, {%0,%1,%2,%3};"
        : "+f"(c[0]), "+f"(c[1]), "+f"(c[2]), "+f"(c[3])
        : "r"(a[0]), "r"(a[1]), "r"(a[2]), "r"(a[3]), "r"(b[0]), "r"(b[1]));
}
__device__ __forceinline__ void mma16f(float* c, const uint32_t* a, const uint32_t* b) {
    asm("mma.sync.aligned.m16n8k16.row.col.f32.f16.f16.f32 "
        "{%0,%1,%2,%3}, {%4,%5,%6,%7}, {%8,%9}, {%0,%1,%2,%3};"
        : "+f"(c[0]), "+f"(c[1]), "+f"(c[2]), "+f"(c[3])
        : "r"(a[0]), "r"(a[1]), "r"(a[2]), "r"(a[3]), "r"(b[0]), "r"(b[1]));
}
__device__ __forceinline__ void mma16h(uint32_t* c, const uint32_t* a, const uint32_t* b) {
    asm("mma.sync.aligned.m16n8k16.row.col.f16.f16.f16.f16 "
        "{%0,%1}, {%2,%3,%4,%5}, {%6,%7}, {%0,%1};"
        : "+r"(c[0]), "+r"(c[1])
        : "r"(a[0]), "r"(a[1]), "r"(a[2]), "r"(a[3]), "r"(b[0]), "r"(b[1]));
}
__device__ __forceinline__ void ldmx4(uint32_t* r, uint32_t a) {
    asm volatile("ldmatrix.sync.aligned.m8n8.x4.shared.b16 {%0,%1,%2,%3}, [%4];"
        : "=r"(r[0]), "=r"(r[1]), "=r"(r[2]), "=r"(r[3]) : "r"(a));
}
__device__ __forceinline__ void ldmx2(uint32_t* r, uint32_t a) {
    asm volatile("ldmatrix.sync.aligned.m8n8.x2.shared.b16 {%0,%1}, [%2];"
        : "=r"(r[0]), "=r"(r[1]) : "r"(a));
}
__device__ __forceinline__ void ldmx2t(uint32_t* r, uint32_t a) {
    asm volatile("ldmatrix.sync.aligned.m8n8.x2.trans.shared.b16 {%0,%1}, [%2];"
        : "=r"(r[0]), "=r"(r[1]) : "r"(a));
}
__device__ __forceinline__ uint32_t smem_u32(const void* p) {
    uint32_t a;
    asm("{ .reg .u64 t; cvta.to.shared.u64 t, %1; cvt.u32.u64 %0, t; }" : "=r"(a) : "l"(p));
    return a;
}
__device__ __forceinline__ void cp16(uint32_t dst, const void* src) {
    asm volatile("cp.async.ca.shared.global [%0], [%1], 16;" :: "r"(dst), "l"(src));
}
__device__ __forceinline__ void cp_commit() { asm volatile("cp.async.commit_group;" ::: "memory"); }
__device__ __forceinline__ void cp_wait0()  { asm volatile("cp.async.wait_group 0;" ::: "memory"); }

// ---------------- weight transpose + split: W[K,N] -> Wh(/Wl)[N,K] fp16 ----------------
__global__ __launch_bounds__(256) void wsplit_kernel(
    const float* __restrict__ W, __half* __restrict__ Wh, __half* __restrict__ Wl,
    int K, int Nn, int ld, size_t wz, size_t oz)
{
    __shared__ float ts[32][33];
    int z = blockIdx.z;
    const float* Wp = W + (size_t)z * wz;
    int n0 = blockIdx.x * 32, k0 = blockIdx.y * 32;
    int tx = threadIdx.x & 31, ty = threadIdx.x >> 5;
    #pragma unroll
    for (int i = 0; i < 4; i++)
        ts[ty + i * 8][tx] = Wp[(size_t)(k0 + ty + i * 8) * ld + n0 + tx];
    __syncthreads();
    #pragma unroll
    for (int i = 0; i < 4; i++) {
        int n = n0 + ty + i * 8, k = k0 + tx;
        float v = ts[tx][ty + i * 8];
        __half h = __float2half(v);
        Wh[(size_t)z * oz + (size_t)n * K + k] = h;
        if (Wl) Wl[(size_t)z * oz + (size_t)n * K + k] = __float2half(v - __half2float(h));
    }
}

// ---------------- fp16 split GEMM ----------------
constexpr int G_AH = 0;
constexpr int G_AL = 10240;
constexpr int G_BH = 20480;
constexpr int G_BL = 30720;
constexpr int G_STG = 40960;
constexpr int G_SMEM = 2 * G_STG;     // 81920

template<int TERMS, bool AHALF, bool HOUT, bool GATHER, bool SCATTER,
         bool BIAS, bool GELU, bool RESID, bool CONDC>
__global__ __launch_bounds__(256) void gemm_tc2(
    const void* __restrict__ Av,
    const __half* __restrict__ Bh, const __half* __restrict__ Bl,
    void* __restrict__ Cv, int M, int Nn, int K,
    const float* __restrict__ bias, int biasz,
    const float* __restrict__ res, const float* __restrict__ condc,
    const int* __restrict__ gidx, const int* __restrict__ cntp,
    size_t wz, size_t azoff, int czoff)
{
    extern __shared__ char sm[];
    int ez = blockIdx.z;
    if (cntp) M = cntp[ez];
    int row0 = blockIdx.y * 128;
    if (row0 >= M) return;
    int col0 = blockIdx.x * 128;

    Bh += (size_t)ez * wz;
    if (TERMS == 3) Bl += (size_t)ez * wz;
    const int* gz = (GATHER || SCATTER) ? (gidx + ez * TT) : nullptr;
    size_t crow_base = (size_t)ez * (size_t)czoff;

    uint32_t sb = smem_u32(sm);
    int tid = threadIdx.x, lane = tid & 31, warp = tid >> 5;
    int m_base = (warp >> 2) * 64, n_base = (warp & 3) * 32;

    int l_row  = tid >> 1;
    int l_half = tid & 1;
    int gar = row0 + l_row;
    bool gav = gar < M;
    int garow = gav ? (GATHER ? gz[gar] : gar) : 0;
    const float* ap = AHALF ? nullptr : ((const float*)Av + (size_t)ez * azoff + (size_t)garow * K);
    const char* aph = AHALF ? (const char*)((const __half*)Av + (size_t)ez * azoff + (size_t)garow * K) : nullptr;
    const char* bhp = (const char*)(Bh + (size_t)(col0 + l_row) * K);
    const char* blp = (TERMS == 3) ? (const char*)(Bl + (size_t)(col0 + l_row) * K) : nullptr;
    uint32_t a_sts = sb + (uint32_t)(l_row * 20 + l_half * 8) * 4;
    uint32_t b_sts = sb + (uint32_t)(l_row * 20 + l_half * 8) * 4;

    uint32_t a_lrow = (uint32_t)(m_base + (lane & 7) + ((lane >> 3) & 1) * 8);
    uint32_t a_lcol = (uint32_t)((lane >> 4) * 4);
    int bl15 = lane & 15;
    uint32_t b_lrow = (uint32_t)(n_base + (bl15 & 7));
    uint32_t b_lcol = (uint32_t)(((bl15 >> 3) & 1) * 4);

    float acc[4][4][4];
    uint32_t accl[4][4][2];
    #pragma unroll
    for (int i = 0; i < 4; i++)
        #pragma unroll
        for (int j = 0; j < 4; j++) {
            #pragma unroll
            for (int q = 0; q < 4; q++) acc[i][j][q] = 0.f;
            accl[i][j][0] = 0u; accl[i][j][1] = 0u;
        }

    int nt = K >> 5;
    float4 pa[4];

    auto ldgA = [&](int kt) {
        const float* p = ap + kt * 32 + l_half * 16;
        if (gav) {
            pa[0] = *(const float4*)(p);
            pa[1] = *(const float4*)(p + 4);
            pa[2] = *(const float4*)(p + 8);
            pa[3] = *(const float4*)(p + 12);
        } else {
            pa[0] = pa[1] = pa[2] = pa[3] = make_float4(0.f, 0.f, 0.f, 0.f);
        }
    };
    auto cpA = [&](int kt, int buf) {
        uint32_t d = a_sts + buf * G_STG;
        const char* sh = aph + (size_t)kt * 64 + l_half * 32;
        cp16(d + G_AH,      sh);
        cp16(d + G_AH + 16, sh + 16);
    };
    auto cpB = [&](int kt, int buf) {
        uint32_t d = b_sts + buf * G_STG;
        const char* sh = bhp + (size_t)kt * 64 + l_half * 32;
        cp16(d + G_BH,      sh);
        cp16(d + G_BH + 16, sh + 16);
        if (TERMS == 3) {
            const char* sl = blp + (size_t)kt * 64 + l_half * 32;
            cp16(d + G_BL,      sl);
            cp16(d + G_BL + 16, sl + 16);
        }
    };
    auto stsA = [&](int buf) {
        uint32_t d = a_sts + buf * G_STG;
        if (TERMS >= 2) {
            uint32_t h[8], l[8];
            hsplit2(pa[0].x, pa[0].y, h[0], l[0]); hsplit2(pa[0].z, pa[0].w, h[1], l[1]);
            hsplit2(pa[1].x, pa[1].y, h[2], l[2]); hsplit2(pa[1].z, pa[1].w, h[3], l[3]);
            hsplit2(pa[2].x, pa[2].y, h[4], l[4]); hsplit2(pa[2].z, pa[2].w, h[5], l[5]);
            hsplit2(pa[3].x, pa[3].y, h[6], l[6]); hsplit2(pa[3].z, pa[3].w, h[7], l[7]);
            *(uint4*)(sm + (d - sb) + G_AH)      = *(uint4*)(h);
            *(uint4*)(sm + (d - sb) + G_AH + 16) = *(uint4*)(h + 4);
            *(uint4*)(sm + (d - sb) + G_AL)      = *(uint4*)(l);
            *(uint4*)(sm + (d - sb) + G_AL + 16) = *(uint4*)(l + 4);
        } else {
            uint32_t h[8];
            h[0] = hpack2(pa[0].x, pa[0].y); h[1] = hpack2(pa[0].z, pa[0].w);
            h[2] = hpack2(pa[1].x, pa[1].y); h[3] = hpack2(pa[1].z, pa[1].w);
            h[4] = hpack2(pa[2].x, pa[2].y); h[5] = hpack2(pa[2].z, pa[2].w);
            h[6] = hpack2(pa[3].x, pa[3].y); h[7] = hpack2(pa[3].z, pa[3].w);
            *(uint4*)(sm + (d - sb) + G_AH)      = *(uint4*)(h);
            *(uint4*)(sm + (d - sb) + G_AH + 16) = *(uint4*)(h + 4);
        }
    };

    if (AHALF) { cpA(0, 0); cpB(0, 0); cp_commit(); }
    else       { ldgA(0); cpB(0, 0); cp_commit(); stsA(0); }
    cp_wait0();
    __syncthreads();

    for (int t = 0; t < nt; t++) {
        int cur = t & 1;
        if (t + 1 < nt) {
            if (AHALF) { cpA(t + 1, cur ^ 1); cpB(t + 1, cur ^ 1); cp_commit(); }
            else       { ldgA(t + 1); cpB(t + 1, cur ^ 1); cp_commit(); }
        }
        uint32_t stage = sb + cur * G_STG;
        #pragma unroll
        for (int j = 0; j < 2; j++) {
            uint32_t a_h[4][4], a_l[4][4], b_h[4][2], b_l[4][2];
            #pragma unroll
            for (int mi = 0; mi < 4; mi++) {
                uint32_t ad = stage + ((a_lrow + mi * 16) * 20 + j * 8 + a_lcol) * 4;
                ldmx4(a_h[mi], ad + G_AH);
                if (TERMS >= 2) ldmx4(a_l[mi], ad + G_AL);
            }
            #pragma unroll
            for (int ni = 0; ni < 4; ni++) {
                uint32_t bd = stage + ((b_lrow + ni * 8) * 20 + j * 8 + b_lcol) * 4;
                ldmx2(b_h[ni], bd + G_BH);
                if (TERMS == 3) ldmx2(b_l[ni], bd + G_BL);
            }
            #pragma unroll
            for (int mi = 0; mi < 4; mi++)
                #pragma unroll
                for (int ni = 0; ni < 4; ni++) {
                    mma16f(acc[mi][ni],  a_h[mi], b_h[ni]);
                    if (TERMS >= 2)
                        mma16h(accl[mi][ni], a_l[mi], b_h[ni]);
                    if (TERMS == 3)
                        mma16h(accl[mi][ni], a_h[mi], b_l[ni]);
                }
        }
        if (t + 1 < nt) {
            if (!AHALF) stsA(cur ^ 1);
            cp_wait0();
            __syncthreads();
        }
    }

    int grp = lane >> 2, qid = lane & 3;
    #pragma unroll
    for (int mi = 0; mi < 4; mi++) {
        int r0 = row0 + m_base + mi * 16 + grp;
        int r1 = r0 + 8;
        bool v0 = r0 < M, v1 = r1 < M;
        size_t cr0 = 0, cr1 = 0;
        if (v0) cr0 = crow_base + (SCATTER ? (size_t)gz[r0] : (size_t)r0);
        if (v1) cr1 = crow_base + (SCATTER ? (size_t)gz[r1] : (size_t)r1);
        #pragma unroll
        for (int ni = 0; ni < 4; ni++) {
            int cb = col0 + n_base + ni * 8 + qid * 2;
            float2 f01 = make_float2(0.f, 0.f), f23 = make_float2(0.f, 0.f);
            if (TERMS >= 2) {
                f01 = __half22float2(*(__half2*)&accl[mi][ni][0]);
                f23 = __half22float2(*(__half2*)&accl[mi][ni][1]);
            }
            #pragma unroll
            for (int hf = 0; hf < 2; hf++) {
                bool valid = hf ? v1 : v0;
                if (!valid) continue;
                int rr = hf ? r1 : r0;
                size_t cr = hf ? cr1 : cr0;
                float e0 = acc[mi][ni][hf * 2 + 0] + (hf ? f23.x : f01.x);
                float e1 = acc[mi][ni][hf * 2 + 1] + (hf ? f23.y : f01.y);
                if (BIAS)  { e0 += bias[biasz * ez + cb]; e1 += bias[biasz * ez + cb + 1]; }
                if (CONDC) {
                    const float* cc = condc + (size_t)(rr >> 8) * Nn + cb;
                    e0 += cc[0]; e1 += cc[1];
                }
                if (GELU)  { e0 = gelu_f(e0); e1 = gelu_f(e1); }
                if (RESID) {
                    const float* rp = res + (size_t)rr * Nn + cb;
                    e0 += rp[0]; e1 += rp[1];
                }
                if (HOUT) {
                    __half2 hv = __floats2half2_rn(e0, e1);
                    *(__half2*)((__half*)Cv + cr * Nn + cb) = hv;
                } else {
                    *(float2*)((float*)Cv + cr * Nn + cb) = make_float2(e0, e1);
                }
            }
        }
    }
}

// ---------------- legacy bf16-split GEMM (tiny condc only) ----------------
__global__ __launch_bounds__(256) void gemm_tc_plain(
    const float* __restrict__ A, const float* __restrict__ Bm, float* __restrict__ C,
    int M, int Nn, int K)
{
    int row0 = blockIdx.y * 128;
    if (row0 >= M) return;
    int col0 = blockIdx.x * 128;
    __shared__ uint32_t Ah[2][128][9];
    __shared__ uint32_t Al[2][128][9];
    __shared__ uint32_t Bh[2][8][132];
    __shared__ uint32_t Bl[2][8][132];
    int tid = threadIdx.x, lane = tid & 31, warp = tid >> 5;
    int grp = lane >> 2, qid = lane & 3;
    int m_base = (warp >> 2) * 64, n_base = (warp & 3) * 32;
    int a_r = tid >> 2, a_k4 = (tid & 3) * 4, a_kp = (tid & 3) * 2;
    int ar1 = row0 + a_r, ar2 = row0 + a_r + 64;
    bool av1 = ar1 < M, av2 = ar2 < M;
    int b_kp = tid >> 5, b_n4 = (tid & 31) * 4;
    float acc[4][4][4];
    #pragma unroll
    for (int i = 0; i < 4; i++)
        #pragma unroll
        for (int j = 0; j < 4; j++)
            #pragma unroll
            for (int q = 0; q < 4; q++) acc[i][j][q] = 0.f;
    int nt = K / 16;
    float4 ra0, ra1, rbE, rbO;
    ra0 = av1 ? *(const float4*)(A + (size_t)ar1 * K + a_k4) : make_float4(0,0,0,0);
    ra1 = av2 ? *(const float4*)(A + (size_t)ar2 * K + a_k4) : make_float4(0,0,0,0);
    rbE = *(const float4*)(Bm + (size_t)(2 * b_kp) * Nn + col0 + b_n4);
    rbO = *(const float4*)(Bm + (size_t)(2 * b_kp + 1) * Nn + col0 + b_n4);
    {
        uint32_t h0, l0, h1, l1;
        bfsplit2(ra0.x, ra0.y, h0, l0); bfsplit2(ra0.z, ra0.w, h1, l1);
        Ah[0][a_r][a_kp] = h0; Ah[0][a_r][a_kp+1] = h1; Al[0][a_r][a_kp] = l0; Al[0][a_r][a_kp+1] = l1;
        bfsplit2(ra1.x, ra1.y, h0, l0); bfsplit2(ra1.z, ra1.w, h1, l1);
        Ah[0][a_r+64][a_kp] = h0; Ah[0][a_r+64][a_kp+1] = h1; Al[0][a_r+64][a_kp] = l0; Al[0][a_r+64][a_kp+1] = l1;
        uint32_t bh4[4], bl4[4];
        bfsplit2(rbE.x, rbO.x, bh4[0], bl4[0]); bfsplit2(rbE.y, rbO.y, bh4[1], bl4[1]);
        bfsplit2(rbE.z, rbO.z, bh4[2], bl4[2]); bfsplit2(rbE.w, rbO.w, bh4[3], bl4[3]);
        *(uint4*)&Bh[0][b_kp][b_n4] = *(uint4*)bh4;
        *(uint4*)&Bl[0][b_kp][b_n4] = *(uint4*)bl4;
    }
    __syncthreads();
    for (int t = 0; t < nt; t++) {
        int cur = t & 1;
        if (t + 1 < nt) {
            int k0 = (t + 1) * 16;
            ra0 = av1 ? *(const float4*)(A + (size_t)ar1 * K + k0 + a_k4) : make_float4(0,0,0,0);
            ra1 = av2 ? *(const float4*)(A + (size_t)ar2 * K + k0 + a_k4) : make_float4(0,0,0,0);
            rbE = *(const float4*)(Bm + (size_t)(k0 + 2 * b_kp) * Nn + col0 + b_n4);
            rbO = *(const float4*)(Bm + (size_t)(k0 + 2 * b_kp + 1) * Nn + col0 + b_n4);
        }
        uint32_t a_h[4][4], a_l[4][4], b_h[4][2], b_l[4][2];
        #pragma unroll
        for (int mi = 0; mi < 4; mi++) {
            int rm = m_base + mi * 16 + grp;
            a_h[mi][0] = Ah[cur][rm][qid];         a_l[mi][0] = Al[cur][rm][qid];
            a_h[mi][1] = Ah[cur][rm + 8][qid];     a_l[mi][1] = Al[cur][rm + 8][qid];
            a_h[mi][2] = Ah[cur][rm][qid + 4];     a_l[mi][2] = Al[cur][rm][qid + 4];
            a_h[mi][3] = Ah[cur][rm + 8][qid + 4]; a_l[mi][3] = Al[cur][rm + 8][qid + 4];
        }
        #pragma unroll
        for (int ni = 0; ni < 4; ni++) {
            int cn = n_base + ni * 8 + grp;
            b_h[ni][0] = Bh[cur][qid][cn];     b_l[ni][0] = Bl[cur][qid][cn];
            b_h[ni][1] = Bh[cur][qid + 4][cn]; b_l[ni][1] = Bl[cur][qid + 4][cn];
        }
        #pragma unroll
        for (int mi = 0; mi < 4; mi++)
            #pragma unroll
            for (int ni = 0; ni < 4; ni++) {
                mma16bf(acc[mi][ni], a_h[mi], b_l[ni]);
                mma16bf(acc[mi][ni], a_l[mi], b_h[ni]);
                mma16bf(acc[mi][ni], a_h[mi], b_h[ni]);
            }
        if (t + 1 < nt) {
            int nxt = (t + 1) & 1;
            uint32_t h0, l0, h1, l1;
            bfsplit2(ra0.x, ra0.y, h0, l0); bfsplit2(ra0.z, ra0.w, h1, l1);
            Ah[nxt][a_r][a_kp] = h0; Ah[nxt][a_r][a_kp+1] = h1; Al[nxt][a_r][a_kp] = l0; Al[nxt][a_r][a_kp+1] = l1;
            bfsplit2(ra1.x, ra1.y, h0, l0); bfsplit2(ra1.z, ra1.w, h1, l1);
            Ah[nxt][a_r+64][a_kp] = h0; Ah[nxt][a_r+64][a_kp+1] = h1; Al[nxt][a_r+64][a_kp] = l0; Al[nxt][a_r+64][a_kp+1] = l1;
            uint32_t bh4[4], bl4[4];
            bfsplit2(rbE.x, rbO.x, bh4[0], bl4[0]); bfsplit2(rbE.y, rbO.y, bh4[1], bl4[1]);
            bfsplit2(rbE.z, rbO.z, bh4[2], bl4[2]); bfsplit2(rbE.w, rbO.w, bh4[3], bl4[3]);
            *(uint4*)&Bh[nxt][b_kp][b_n4] = *(uint4*)bh4;
            *(uint4*)&Bl[nxt][b_kp][b_n4] = *(uint4*)bl4;
            __syncthreads();
        }
    }
    #pragma unroll
    for (int mi = 0; mi < 4; mi++) {
        int r0 = row0 + m_base + mi * 16 + grp;
        int r1 = r0 + 8;
        #pragma unroll
        for (int ni = 0; ni < 4; ni++) {
            int cb = col0 + n_base + ni * 8 + qid * 2;
            if (r0 < M) *(float2*)(C + (size_t)r0 * Nn + cb) = make_float2(acc[mi][ni][0], acc[mi][ni][1]);
            if (r1 < M) *(float2*)(C + (size_t)r1 * Nn + cb) = make_float2(acc[mi][ni][2], acc[mi][ni][3]);
        }
    }
}

// ---------------- LayerNorm ----------------
__global__ __launch_bounds__(256) void ln_kernel(
    const float* __restrict__ x, const float* __restrict__ g,
    const float* __restrict__ bta, float* __restrict__ out)
{
    int t = blockIdx.x, tid = threadIdx.x;
    float4 v = ((const float4*)(x + (size_t)t * DIM))[tid];
    float s  = v.x + v.y + v.z + v.w;
    float sq = v.x * v.x + v.y * v.y + v.z * v.z + v.w * v.w;
    __shared__ float sh[8], sh2[8];
    float ws = warpsum(s), wq = warpsum(sq);
    if ((tid & 31) == 0) { sh[tid >> 5] = ws; sh2[tid >> 5] = wq; }
    __syncthreads();
    if (tid < 32) {
        float a  = (tid < 8) ? sh[tid]  : 0.f;
        float b2 = (tid < 8) ? sh2[tid] : 0.f;
        a = warpsum(a); b2 = warpsum(b2);
        if (tid == 0) { sh[0] = a; sh2[0] = b2; }
    }
    __syncthreads();
    float mu  = sh[0] * (1.0f / DIM);
    float var = sh2[0] * (1.0f / DIM) - mu * mu;
    float inv = rsqrtf(var + 1e-5f);
    float4 gg = ((const float4*)g)[tid], bb = ((const float4*)bta)[tid];
    float4 o;
    o.x = (v.x - mu) * inv * gg.x + bb.x;
    o.y = (v.y - mu) * inv * gg.y + bb.y;
    o.z = (v.z - mu) * inv * gg.z + bb.z;
    o.w = (v.w - mu) * inv * gg.w + bb.w;
    ((float4*)(out + (size_t)t * DIM))[tid] = o;
}

// ---------------- fused attention: scores + softmax + PV in one kernel ----------------
// one CTA per (64-q-tile, batch*head); 128 threads; dynamic smem:
//   Qs  u32[64][36]      @ 0       (9216 B)
//   KVs u32[64][36]      @ 9216    (9216 B)
//   Ssm float[64][264]   @ 18432   (67584 B)
//   Ps4 u32[4][64][36]   @ 86016   (36864 B)   total 122880 B
constexpr int AF_QS = 0;
constexpr int AF_KV = 9216;
constexpr int AF_S  = 18432;
constexpr int AF_P  = 86016;
constexpr int AF_SMEM = 122880;

__global__ __launch_bounds__(128) void attn_fused(
    const __half* __restrict__ qkv, float* __restrict__ o)
{
    extern __shared__ char sm[];
    int qt = blockIdx.x, bh = blockIdx.y;
    int b = bh >> 4, h = bh & 15;
    int tid = threadIdx.x, lane = tid & 31, warp = tid >> 5;
    int l_row = tid >> 1, l_half = tid & 1;

    uint32_t sb = smem_u32(sm);
    uint32_t qbase = sb + AF_QS, kvbase = sb + AF_KV, pbase = sb + AF_P;
    float* Ssm = (float*)(sm + AF_S);

    // load Q tile (persistent)
    {
        const __half* qp = qkv + (size_t)(b * NSEQ + qt * 64 + l_row) * 3 * DIM + h * HDIM + l_half * 32;
        char* dst = sm + AF_QS + (l_row * 36 + l_half * 16) * 4;
        #pragma unroll
        for (int i = 0; i < 4; i++)
            *(uint4*)(dst + i * 16) = *(const uint4*)(qp + i * 8);
    }

    int m_base = warp * 16;
    uint32_t a_lrow = (uint32_t)(m_base + (lane & 7) + ((lane >> 3) & 1) * 8);
    uint32_t a_lcol = (uint32_t)((lane >> 4) * 4);
    int bl15 = lane & 15;
    int grp = lane >> 2, qid = lane & 3;

    // ---------- phase 1: S = 0.125 * Q K^T into smem ----------
    for (int kt = 0; kt < 4; kt++) {
        {
            const __half* kp = qkv + (size_t)(b * NSEQ + kt * 64 + l_row) * 3 * DIM + DIM + h * HDIM + l_half * 32;
            char* dst = sm + AF_KV + (l_row * 36 + l_half * 16) * 4;
            #pragma unroll
            for (int i = 0; i < 4; i++)
                *(uint4*)(dst + i * 16) = *(const uint4*)(kp + i * 8);
        }
        __syncthreads();
        float accS[8][4];
        #pragma unroll
        for (int i = 0; i < 8; i++)
            #pragma unroll
            for (int q = 0; q < 4; q++) accS[i][q] = 0.f;
        #pragma unroll
        for (int j = 0; j < 4; j++) {
            uint32_t af[4];
            ldmx4(af, qbase + (a_lrow * 36 + j * 8 + a_lcol) * 4);
            #pragma unroll
            for (int ni = 0; ni < 8; ni++) {
                uint32_t bf[2];
                ldmx2(bf, kvbase + ((uint32_t)(ni * 8 + (bl15 & 7)) * 36 + j * 8 + ((bl15 >> 3) & 1) * 4) * 4);
                mma16f(accS[ni], af, bf);
            }
        }
        int r0 = m_base + grp;
        #pragma unroll
        for (int ni = 0; ni < 8; ni++) {
            int col = kt * 64 + ni * 8 + qid * 2;
            *(float2*)(Ssm + (size_t)r0 * 264 + col)       = make_float2(accS[ni][0] * 0.125f, accS[ni][1] * 0.125f);
            *(float2*)(Ssm + (size_t)(r0 + 8) * 264 + col) = make_float2(accS[ni][2] * 0.125f, accS[ni][3] * 0.125f);
        }
        __syncthreads();
    }

    // ---------- phase 2: softmax rows in smem -> P fp16 tiles ----------
    // warp w handles rows w*16 .. w*16+15; lane L owns cols [8L, 8L+8)
    for (int i = 0; i < 16; i++) {
        int row = warp * 16 + i;
        float* rp = Ssm + (size_t)row * 264 + lane * 8;
        float4 va = *(float4*)(rp);
        float4 vb = *(float4*)(rp + 4);
        float m = fmaxf(fmaxf(fmaxf(va.x, va.y), fmaxf(va.z, va.w)),
                        fmaxf(fmaxf(vb.x, vb.y), fmaxf(vb.z, vb.w)));
        m = warpmax(m);
        float e0 = expf(va.x - m), e1 = expf(va.y - m), e2 = expf(va.z - m), e3 = expf(va.w - m);
        float e4 = expf(vb.x - m), e5 = expf(vb.y - m), e6 = expf(vb.z - m), e7 = expf(vb.w - m);
        float s = e0 + e1 + e2 + e3 + e4 + e5 + e6 + e7;
        s = warpsum(s);
        float inv = 1.0f / s;
        uint32_t hp[4];
        hp[0] = hpack2(e0 * inv, e1 * inv);
        hp[1] = hpack2(e2 * inv, e3 * inv);
        hp[2] = hpack2(e4 * inv, e5 * inv);
        hp[3] = hpack2(e6 * inv, e7 * inv);
        // chunk c = lane/8; u32 idx within tile row = (lane%8)*4
        uint32_t pd = pbase + ((uint32_t)((lane >> 3) * 64 * 36 + row * 36 + (lane & 7) * 4)) * 4;
        *(uint4*)(sm + (pd - sb)) = *(uint4*)hp;
    }
    __syncthreads();

    // ---------- phase 3: O = P V ----------
    float accO[8][4];
    #pragma unroll
    for (int i = 0; i < 8; i++)
        #pragma unroll
        for (int q = 0; q < 4; q++) accO[i][q] = 0.f;

    for (int c = 0; c < 4; c++) {
        {
            const __half* vp = qkv + (size_t)(b * NSEQ + c * 64 + l_row) * 3 * DIM + 2 * DIM + h * HDIM + l_half * 32;
            char* dst = sm + AF_KV + (l_row * 36 + l_half * 16) * 4;
            #pragma unroll
            for (int i = 0; i < 4; i++)
                *(uint4*)(dst + i * 16) = *(const uint4*)(vp + i * 8);
        }
        __syncthreads();
        uint32_t pc = pbase + (uint32_t)(c * 64 * 36) * 4;
        #pragma unroll
        for (int j = 0; j < 4; j++) {
            uint32_t af[4];
            ldmx4(af, pc + (a_lrow * 36 + j * 8 + a_lcol) * 4);
            #pragma unroll
            for (int ni = 0; ni < 8; ni++) {
                uint32_t bf[2];
                ldmx2t(bf, kvbase + ((uint32_t)(j * 16 + bl15) * 36 + ni * 4) * 4);
                mma16f(accO[ni], af, bf);
            }
        }
        __syncthreads();
    }

    int r0 = qt * 64 + m_base + grp;
    #pragma unroll
    for (int ni = 0; ni < 8; ni++) {
        int d = ni * 8 + qid * 2;
        *(float2*)(o + (size_t)(b * NSEQ + r0) * DIM + h * HDIM + d)     = make_float2(accO[ni][0], accO[ni][1]);
        *(float2*)(o + (size_t)(b * NSEQ + r0 + 8) * DIM + h * HDIM + d) = make_float2(accO[ni][2], accO[ni][3]);
    }
}

// ---------------- router ----------------
__global__ __launch_bounds__(128) void router_kernel(
    const float* __restrict__ gh, const float* __restrict__ W, const float* __restrict__ bias)
{
    int t = blockIdx.x;
    int wid = threadIdx.x >> 5, lane = threadIdx.x & 31;
    const float* row = gh + (size_t)t * RHC;
    float s = 0.f;
    for (int k = lane; k < RHC; k += 32) s += row[k] * W[k * NE + wid];
    s = warpsum(s);
    __shared__ float logits[NE];
    if (lane == 0) logits[wid] = s + bias[wid];
    __syncthreads();
    if (threadIdx.x == 0) {
        float l[NE], m = -1e30f;
        #pragma unroll
        for (int e = 0; e < NE; e++) { l[e] = logits[e]; m = fmaxf(m, l[e]); }
        float ssum = 0.f;
        #pragma unroll
        for (int e = 0; e < NE; e++) { l[e] = expf(l[e] - m); ssum += l[e]; }
        float p[NE];
        #pragma unroll
        for (int e = 0; e < NE; e++)
            p[e] = fminf(fmaxf(l[e] / ssum, 1e-9f), 1.0f - 1e-9f);
        int i1 = 0;
        #pragma unroll
        for (int e = 1; e < NE; e++) if (p[e] > p[i1]) i1 = e;
        int i2 = -1;
        #pragma unroll
        for (int e = 0; e < NE; e++) {
            if (e == i1) continue;
            if (i2 < 0 || p[e] > p[i2]) i2 = e;
        }
        float wsum = p[i1] + p[i2];
        int pos = atomicAdd(&g_cnt[i1], 1);
        g_idx[i1 * TT + pos] = t;
        pos = atomicAdd(&g_cnt[i2], 1);
        g_idx[i2 * TT + pos] = t;
        g_te[t] = make_int2(i1, i2);
        g_tw[t] = make_float2(p[i1] / wsum, p[i2] / wsum);
    }
}

__global__ void zero_cnt_kernel() {
    if (threadIdx.x < NE) g_cnt[threadIdx.x] = 0;
}

// out[t] = x1[t] + w1*eout[e1][t] + w2*eout[e2][t]  (eout fp16)
__global__ __launch_bounds__(256) void combine_kernel(
    const float* __restrict__ x1, const __half* __restrict__ eout, float* __restrict__ out)
{
    int t = blockIdx.x, c = threadIdx.x;
    int2 e = g_te[t];
    float2 w = g_tw[t];
    float4 a  = ((const float4*)(x1 + (size_t)t * DIM))[c];
    const __half* p1 = eout + ((size_t)e.x * TT + t) * DIM + c * 4;
    const __half* p2 = eout + ((size_t)e.y * TT + t) * DIM + c * 4;
    float2 v1a = __half22float2(*(const __half2*)(p1));
    float2 v1b = __half22float2(*(const __half2*)(p1 + 2));
    float2 v2a = __half22float2(*(const __half2*)(p2));
    float2 v2b = __half22float2(*(const __half2*)(p2 + 2));
    float4 r;
    r.x = a.x + w.x * v1a.x + w.y * v2a.x;
    r.y = a.y + w.x * v1a.y + w.y * v2a.y;
    r.z = a.z + w.x * v1b.x + w.y * v2b.x;
    r.w = a.w + w.x * v1b.y + w.y * v2b.y;
    ((float4*)(out + (size_t)t * DIM))[c] = r;
}

// ---------------- host launcher ----------------
static void* symaddr(const void* s) {
    void* p = nullptr;
    cudaGetSymbolAddress(&p, s);
    return p;
}

extern "C" void kernel_launch(void* const* d_in, const int* in_sizes, int n_in,
                              void* d_out, int out_size) {
    const float* x       = (const float*)d_in[0];
    const float* cond    = (const float*)d_in[1];
    const float* ln1_g   = (const float*)d_in[2];
    const float* ln1_b   = (const float*)d_in[3];
    const float* qkv_w   = (const float*)d_in[4];
    const float* proj_w  = (const float*)d_in[5];
    const float* proj_b  = (const float*)d_in[6];
    const float* ln2_g   = (const float*)d_in[7];
    const float* ln2_b   = (const float*)d_in[8];
    const float* r_fc1_w = (const float*)d_in[9];
    const float* r_fc1_b = (const float*)d_in[10];
    const float* r_fc2_w = (const float*)d_in[11];
    const float* r_fc2_b = (const float*)d_in[12];
    const float* e_w1    = (const float*)d_in[13];
    const float* e_b1    = (const float*)d_in[14];
    const float* e_w2    = (const float*)d_in[15];
    const float* e_b2    = (const float*)d_in[16];
    float* out = (float*)d_out;

    float*  h1    = (float*)symaddr(g_h1);
    __half* qkv   = (__half*)symaddr(g_qkv);
    float*  o     = (float*)symaddr(g_o);
    float*  x1    = (float*)symaddr(g_x1);
    float*  h2    = (float*)symaddr(g_h2);
    float*  condc = (float*)symaddr(g_condc);
    float*  gh    = (float*)symaddr(g_gh);
    __half* hid   = (__half*)symaddr(g_hid);
    __half* eout  = (__half*)symaddr(g_eout);
    int*    cnt   = (int*)symaddr(g_cnt);
    int*    idx   = (int*)symaddr(g_idx);
    __half* wqkv_h  = (__half*)symaddr(g_wqkv_h);
    __half* wproj_h = (__half*)symaddr(g_wproj_h);
    __half* wfc1_h  = (__half*)symaddr(g_wfc1_h);
    __half* wfc1_l  = (__half*)symaddr(g_wfc1_l);
    __half* we1_h   = (__half*)symaddr(g_we1_h);
    __half* we2_h   = (__half*)symaddr(g_we2_h);

    cudaFuncSetAttribute(gemm_tc2<1,false,true,false,false,false,false,false,false>,
                         cudaFuncAttributeMaxDynamicSharedMemorySize, G_SMEM);
    cudaFuncSetAttribute(gemm_tc2<2,false,false,false,false,true,false,true,false>,
                         cudaFuncAttributeMaxDynamicSharedMemorySize, G_SMEM);
    cudaFuncSetAttribute(gemm_tc2<3,false,false,false,false,true,true,false,true>,
                         cudaFuncAttributeMaxDynamicSharedMemorySize, G_SMEM);
    cudaFuncSetAttribute(gemm_tc2<1,false,true,true,false,true,true,false,false>,
                         cudaFuncAttributeMaxDynamicSharedMemorySize, G_SMEM);
    cudaFuncSetAttribute(gemm_tc2<1,true,true,false,true,true,false,false,false>,
                         cudaFuncAttributeMaxDynamicSharedMemorySize, G_SMEM);
    cudaFuncSetAttribute(attn_fused,
                         cudaFuncAttributeMaxDynamicSharedMemorySize, AF_SMEM);

    zero_cnt_kernel<<<1, 32>>>();

    // pre-split weights: fc1 keeps hi+lo (router precision); qkv/proj/experts hi only
    wsplit_kernel<<<dim3(3 * DIM / 32, DIM / 32, 1), 256>>>(qkv_w, wqkv_h, nullptr, DIM, 3 * DIM, 3 * DIM, 0, 0);
    wsplit_kernel<<<dim3(DIM / 32, DIM / 32, 1), 256>>>(proj_w, wproj_h, nullptr, DIM, DIM, DIM, 0, 0);
    wsplit_kernel<<<dim3(RHC / 32, DIM / 32, 1), 256>>>(r_fc1_w, wfc1_h, wfc1_l, DIM, RHC, RHC, 0, 0);
    wsplit_kernel<<<dim3(DFFC / 32, DIM / 32, NE), 256>>>(e_w1, we1_h, nullptr, DIM, DFFC, DFFC,
                                                          (size_t)DIM * DFFC, (size_t)DFFC * DIM);
    wsplit_kernel<<<dim3(DIM / 32, DFFC / 32, NE), 256>>>(e_w2, we2_h, nullptr, DFFC, DIM, DIM,
                                                          (size_t)DFFC * DIM, (size_t)DIM * DFFC);

    // LN1
    ln_kernel<<<TT, 256>>>(x, ln1_g, ln1_b, h1);

    // QKV = h1 @ qkv_w (1-term) -> fp16
    gemm_tc2<1,false,true,false,false,false,false,false,false>
        <<<dim3(3 * DIM / 128, TT / 128, 1), 256, G_SMEM>>>(h1, wqkv_h, nullptr, qkv, TT, 3 * DIM, DIM,
            nullptr, 0, nullptr, nullptr, nullptr, nullptr, 0, 0, 0);

    // fused attention (scores + softmax + PV)
    attn_fused<<<dim3(4, BB * NH), 128, AF_SMEM>>>(qkv, o);

    // x1 = x + o @ proj_w + proj_b (2-term)
    gemm_tc2<2,false,false,false,false,true,false,true,false>
        <<<dim3(DIM / 128, TT / 128, 1), 256, G_SMEM>>>(o, wproj_h, nullptr, x1, TT, DIM, DIM,
            proj_b, 0, x, nullptr, nullptr, nullptr, 0, 0, 0);

    // LN2
    ln_kernel<<<TT, 256>>>(x1, ln2_g, ln2_b, h2);

    // condc (tiny; legacy bf16 3-term)
    gemm_tc_plain<<<dim3(RHC / 128, 1), 256>>>(cond, r_fc1_w + (size_t)DIM * RHC, condc, BB, RHC, CDIM);

    // gh = gelu(h2 @ r_fc1_w[:D] + condc[b] + b1) (3-term — router precision critical)
    gemm_tc2<3,false,false,false,false,true,true,false,true>
        <<<dim3(RHC / 128, TT / 128, 1), 256, G_SMEM>>>(h2, wfc1_h, wfc1_l, gh, TT, RHC, DIM,
            r_fc1_b, 0, nullptr, condc, nullptr, nullptr, 0, 0, 0);

    // router
    router_kernel<<<TT, 128>>>(gh, r_fc2_w, r_fc2_b);

    // experts (1-term fp16), merged across NE; hid/eout fp16
    gemm_tc2<1,false,true,true,false,true,true,false,false>
        <<<dim3(DFFC / 128, TT / 128, NE), 256, G_SMEM>>>(h2, we1_h, nullptr, hid,
            TT, DFFC, DIM, e_b1, DFFC, nullptr, nullptr,
            idx, cnt, (size_t)DFFC * DIM, 0, TT);
    gemm_tc2<1,true,true,false,true,true,false,false,false>
        <<<dim3(DIM / 128, TT / 128, NE), 256, G_SMEM>>>(hid, we2_h, nullptr, eout,
            TT, DIM, DFFC, e_b2, DIM, nullptr, nullptr,
            idx, cnt, (size_t)DIM * DFFC, (size_t)TT * DFFC, TT);

    // out = x1 + w1*eout[e1] + w2*eout[e2]
    combine_kernel<<<TT, 256>>>(x1, eout, out);
}